// round 9
// baseline (speedup 1.0000x reference)
#include <cuda_runtime.h>
#include <cuda_fp16.h>
#include <cstdint>

// ============================ problem constants ============================
#define SS 2048
#define DD 4096
#define VV 32000
#define MROWS 4094          // B*(S-1)
#define MPAD  4096          // padded GEMM M
#define NTILES 8000         // 32 m-tiles x 250 n-tiles

// scratch (device globals — allocation-free rule), fp16 operands
// A fragment layout (mma.m16n8k16 A): [m16_blk(256)][k16(256)][lane(32)][a0..a3] (16B/lane)
__device__ __half g_act[(size_t)MPAD * DD];
// B pair-packed layout: [n8_blk(4000)][ksp(128)][lane(32)][b0e,b1e,b0o,b1o] (16B/lane)
__device__ __half g_w[(size_t)VV * DD];

// ============================ helpers ============================
__device__ __forceinline__ uint32_t smem_u32(const void* p) {
    uint32_t a;
    asm("{ .reg .u64 t; cvta.to.shared.u64 t, %1; cvt.u32.u64 %0, t; }" : "=r"(a) : "l"(p));
    return a;
}
__device__ __forceinline__ void cp16(uint32_t dst, const void* src) {
    asm volatile("cp.async.cg.shared.global [%0], [%1], 16;" :: "r"(dst), "l"(src));
}
#define CP_COMMIT() asm volatile("cp.async.commit_group;" ::: "memory")
#define CP_WAIT2()  asm volatile("cp.async.wait_group 2;" ::: "memory")

__device__ __forceinline__ void mma_f16(float* d, const uint32_t* a, uint32_t b0, uint32_t b1) {
    asm volatile(
        "mma.sync.aligned.m16n8k16.row.col.f32.f16.f16.f32 "
        "{%0,%1,%2,%3}, {%4,%5,%6,%7}, {%8,%9}, {%0,%1,%2,%3};"
        : "+f"(d[0]), "+f"(d[1]), "+f"(d[2]), "+f"(d[3])
        : "r"(a[0]), "r"(a[1]), "r"(a[2]), "r"(a[3]), "r"(b0), "r"(b1));
}

__device__ __forceinline__ uint32_t packh2(float lo, float hi) {
    __half2 h = __floats2half2_rn(lo, hi);
    return *reinterpret_cast<uint32_t*>(&h);
}

// ============================ prolog kernels ============================
// Permute + fp16-round lm_head_weight [VV, DD] -> g_w pair-packed fragment layout
// (numerics/layout validated in R7: identical rel_err to K-major version).
__global__ void __launch_bounds__(256) wperm_kernel(const float* __restrict__ w,
                                                    uint4* __restrict__ o) {
    int gid = blockIdx.x * 256 + threadIdx.x;      // (VV/8)*128*32 threads
    int lane = gid & 31;
    int ksp  = (gid >> 5) & 127;
    int n8b  = gid >> 12;
    int c = lane & 3;
    int n = n8b * 8 + (lane >> 2);
    const float2* src = reinterpret_cast<const float2*>(w + (size_t)n * DD + ksp * 32 + 2 * c);
    float2 e0 = src[0];    // k = 2c, 2c+1        (even k16, b0)
    float2 e1 = src[4];    // k = 2c+8, 2c+9      (even k16, b1)
    float2 o0 = src[8];    // k = 16+2c, ...      (odd k16, b0)
    float2 o1 = src[12];   // k = 24+2c, ...      (odd k16, b1)
    uint4 v;
    v.x = packh2(e0.x, e0.y);
    v.y = packh2(e1.x, e1.y);
    v.z = packh2(o0.x, o0.y);
    v.w = packh2(o1.x, o1.y);
    o[gid] = v;
}

// RMSNorm one (shifted) row per block, fp16-rounded, A fragment layout.
__global__ void __launch_bounds__(256) rmsperm_kernel(const float* __restrict__ x,
                                                      const float* __restrict__ w,
                                                      uint32_t* __restrict__ o) {
    __shared__ float red[8];
    int r = blockIdx.x, t = threadIdx.x;
    float vals[16];
    if (r < MROWS) {
        int b = r / (SS - 1);
        int s = r - b * (SS - 1);
        const float4* xr = reinterpret_cast<const float4*>(x + ((size_t)b * SS + s) * DD + t * 16);
        const float4* wr = reinterpret_cast<const float4*>(w + t * 16);
        float4 q[4];
        float acc = 0.f;
#pragma unroll
        for (int i = 0; i < 4; ++i) {
            q[i] = xr[i];
            acc += q[i].x * q[i].x + q[i].y * q[i].y + q[i].z * q[i].z + q[i].w * q[i].w;
        }
#pragma unroll
        for (int off = 16; off; off >>= 1) acc += __shfl_xor_sync(0xffffffffu, acc, off);
        if ((t & 31) == 0) red[t >> 5] = acc;
        __syncthreads();
        float tot = red[0] + red[1] + red[2] + red[3] + red[4] + red[5] + red[6] + red[7];
        float rs = rsqrtf(tot * (1.0f / DD) + 1e-6f);
#pragma unroll
        for (int i = 0; i < 4; ++i) {
            float4 wv = wr[i];
            vals[4 * i + 0] = q[i].x * rs * wv.x;
            vals[4 * i + 1] = q[i].y * rs * wv.y;
            vals[4 * i + 2] = q[i].z * rs * wv.z;
            vals[4 * i + 3] = q[i].w * rs * wv.w;
        }
    } else {
#pragma unroll
        for (int i = 0; i < 16; ++i) vals[i] = 0.f;
        __syncthreads();
    }
    int m16 = r >> 4, ri = r & 15;
    int slotb = ri >> 3;
    size_t laneBase = ((size_t)m16 * 256 + t) * 32 + (ri & 7) * 4;
#pragma unroll
    for (int c = 0; c < 4; ++c) {
        size_t li = (laneBase + c) * 4;
        o[li + slotb]     = packh2(vals[2 * c],     vals[2 * c + 1]);
        o[li + slotb + 2] = packh2(vals[2 * c + 8], vals[2 * c + 9]);
    }
}

// Shifted labels -> float32 tail of d_out (layout proven in R3/R4).
__global__ void __launch_bounds__(256) labels_kernel(const int* __restrict__ lab,
                                                     float* __restrict__ out, long long rem) {
    int i = blockIdx.x * blockDim.x + threadIdx.x;
    if (i >= MROWS) return;
    int b = i / (SS - 1);
    int s = i - b * (SS - 1);
    int v = lab[(size_t)b * SS + s + 1];
    size_t base = (size_t)MROWS * VV;
    if (rem >= 2LL * MROWS) {
        reinterpret_cast<long long*>(out + base)[i] = (long long)v;
    } else if (rem >= (long long)MROWS) {
        out[base + i] = (float)v;
    }
}

// ============================ GEMM kernel (persistent) ============================
// CTA 128x128, kBlock 64, 3-stage cp.async pipeline with R6's two-sync structure.
// Persistent CTAs: pipeline streams across tile boundaries (no per-tile fill bubble).
#define NSTG      3
#define STG_BYTES 32768                 // A 16KB + B 16KB per stage
#define KBLOCKS   (DD / 64)             // 64
#define TILE_BYTES_A (8ull * 256 * 512)     // per m_tile: 1 MiB
#define TILE_BYTES_B (16ull * 128 * 512)    // per n_tile: 1 MiB

__global__ void __launch_bounds__(256, 2) gemm_kernel(const __half* __restrict__ A,
                                                      const __half* __restrict__ B,
                                                      float* __restrict__ out) {
    extern __shared__ char smem[];
    uint32_t sbase = smem_u32(smem);
    int t = threadIdx.x;
    int lane = t & 31, wid = t >> 5;
    int wm = wid & 3, wn = wid >> 2;
    int G = gridDim.x;
    int p = blockIdx.x;
    if (p >= NTILES) return;

    const char* Ab = (const char*)A;
    const char* Bb = (const char*)B;

    // load one 64-wide k-chunk into stage st; tile bases passed as byte offsets
    auto load_stage = [&](int st, size_t offA, size_t offB, int kb) {
        uint32_t dstA = sbase + st * STG_BYTES;
        uint32_t dstB = dstA + 16384;
#pragma unroll
        for (int pp = 0; pp < 4; ++pp) {            // A: 1024 x 16B chunks
            int q = pp * 256 + t;                   // q = (m16b*4 + ks)*32 + ln
            int ln = q & 31, ks = (q >> 5) & 3, m16b = q >> 7;
            const char* src = Ab + offA + ((((size_t)m16b * 256 + kb * 4 + ks) * 32 + ln) << 4);
            cp16(dstA + (q << 4), src);
        }
#pragma unroll
        for (int pp = 0; pp < 4; ++pp) {            // B: 1024 x 16B chunks
            int q = pp * 256 + t;                   // q = (n8b*2 + kspl)*32 + ln
            int ln = q & 31, kspl = (q >> 5) & 1, n8b = q >> 6;
            const char* src = Bb + offB + ((((size_t)n8b * 128 + kb * 2 + kspl) * 32 + ln) << 4);
            cp16(dstB + (q << 4), src);
        }
    };

    // ---- load cursor (runs NSTG chunks ahead through my (tile, kb) stream)
    int ld_tile = p, ld_kb = 0;
    size_t ld_offA = (size_t)(ld_tile & 31) * TILE_BYTES_A;
    size_t ld_offB = (size_t)(ld_tile >> 5) * TILE_BYTES_B;
    auto ld_advance = [&]() {
        if (++ld_kb == KBLOCKS) {
            ld_kb = 0;
            ld_tile += G;
            if (ld_tile < NTILES) {
                ld_offA = (size_t)(ld_tile & 31) * TILE_BYTES_A;
                ld_offB = (size_t)(ld_tile >> 5) * TILE_BYTES_B;
            }
        }
    };

    // prologue: fill 3 stages (KBLOCKS >= 3 so all within first tile)
#pragma unroll
    for (int s = 0; s < NSTG; ++s) {
        load_stage(s, ld_offA, ld_offB, ld_kb);
        CP_COMMIT();
        ld_advance();
    }

    int st = 0;
    int gq = lane >> 2, tq = lane & 3;

    for (int tile = p; tile < NTILES; tile += G) {
        int m_tile = tile & 31, n_tile = tile >> 5;

        float acc[2][8][4];
#pragma unroll
        for (int i = 0; i < 2; ++i)
#pragma unroll
            for (int j = 0; j < 8; ++j)
#pragma unroll
                for (int c = 0; c < 4; ++c) acc[i][j][c] = 0.f;

        for (int kb = 0; kb < KBLOCKS; ++kb) {
            CP_WAIT2();                 // oldest of 3 pending groups (this stage) done
            __syncthreads();

            const uint4* Asp = reinterpret_cast<const uint4*>(smem + st * STG_BYTES);
            const uint4* Bsp = reinterpret_cast<const uint4*>(smem + st * STG_BYTES + 16384);
#pragma unroll
            for (int kspl = 0; kspl < 2; ++kspl) {
                uint4 bf[8];                           // 8 lds.128: B for both ks halves
#pragma unroll
                for (int j = 0; j < 8; ++j)
                    bf[j] = Bsp[(((wn * 8 + j) * 2 + kspl) * 32) + lane];
#pragma unroll
                for (int ks2 = 0; ks2 < 2; ++ks2) {
                    int ks = kspl * 2 + ks2;
                    uint4 a[2];                        // 2 lds.128
#pragma unroll
                    for (int i = 0; i < 2; ++i)
                        a[i] = Asp[(((wm * 2 + i) * 4 + ks) * 32) + lane];
#pragma unroll
                    for (int i = 0; i < 2; ++i)
#pragma unroll
                        for (int j = 0; j < 8; ++j) {
                            uint32_t b0 = ks2 ? bf[j].z : bf[j].x;
                            uint32_t b1 = ks2 ? bf[j].w : bf[j].y;
                            mma_f16(acc[i][j], (const uint32_t*)&a[i], b0, b1);
                        }
                }
            }
            __syncthreads();            // stage st fully consumed -> safe to refill
            if (ld_tile < NTILES) {
                load_stage(st, ld_offA, ld_offB, ld_kb);
                ld_advance();
            }
            CP_COMMIT();                // unconditional: keeps wait2 accounting exact
            st = (st == NSTG - 1) ? 0 : st + 1;
        }

        // epilogue (next tile's loads already in flight)
#pragma unroll
        for (int i = 0; i < 2; ++i) {
            int r0 = m_tile * 128 + wm * 32 + i * 16 + gq;
#pragma unroll
            for (int j = 0; j < 8; ++j) {
                int col = n_tile * 128 + wn * 64 + j * 8 + tq * 2;
                if (r0 < MROWS)
                    *reinterpret_cast<float2*>(out + (size_t)r0 * VV + col) =
                        make_float2(acc[i][j][0], acc[i][j][1]);
                if (r0 + 8 < MROWS)
                    *reinterpret_cast<float2*>(out + (size_t)(r0 + 8) * VV + col) =
                        make_float2(acc[i][j][2], acc[i][j][3]);
            }
        }
    }
}

// ============================ host launcher ============================
extern "C" void kernel_launch(void* const* d_in, const int* in_sizes, int n_in,
                              void* d_out, int out_size) {
    const float* hs  = (const float*)d_in[0];
    const float* nw  = (const float*)d_in[1];
    const float* lmw = (const float*)d_in[2];
    const int*   lab = (const int*)d_in[4];
    float* out = (float*)d_out;

    void* act_ptr = nullptr; cudaGetSymbolAddress(&act_ptr, g_act);
    void* w_ptr   = nullptr; cudaGetSymbolAddress(&w_ptr, g_w);

    // prolog: permute/round weights + rmsnorm activations + labels
    wperm_kernel<<<(VV / 8) * 128 * 32 / 256, 256>>>(lmw, (uint4*)w_ptr);
    rmsperm_kernel<<<MPAD, 256>>>(hs, nw, (uint32_t*)act_ptr);
    long long rem = (long long)out_size - (long long)MROWS * VV;
    labels_kernel<<<(MROWS + 255) / 256, 256>>>(lab, out, rem);

    // GEMM: persistent, 2 CTAs per SM
    int dev = 0, smCount = 148;
    cudaGetDevice(&dev);
    cudaDeviceGetAttribute(&smCount, cudaDevAttrMultiProcessorCount, dev);
    int grid = 2 * smCount;
    if (grid > NTILES) grid = NTILES;
    cudaFuncSetAttribute(gemm_kernel, cudaFuncAttributeMaxDynamicSharedMemorySize,
                         NSTG * STG_BYTES);
    gemm_kernel<<<grid, 256, NSTG * STG_BYTES>>>((const __half*)act_ptr,
                                                 (const __half*)w_ptr, out);
}

// round 10
// speedup vs baseline: 1.6285x; 1.6285x over previous
#include <cuda_runtime.h>
#include <cuda_fp16.h>
#include <cstdint>

// ============================ problem constants ============================
#define SS 2048
#define DD 4096
#define VV 32000
#define MROWS 4094          // B*(S-1)
#define MPAD  4096          // padded GEMM M

// scratch (device globals — allocation-free rule), fp16 operands
// A fragment layout (mma.m16n8k16 A): [m16_blk(256)][k16(256)][lane(32)][a0..a3] (16B/lane)
__device__ __half g_act[(size_t)MPAD * DD];
// B pair-packed layout: [n8_blk(4000)][ksp(128)][lane(32)][b0e,b1e,b0o,b1o] (16B/lane)
__device__ __half g_w[(size_t)VV * DD];

// ============================ helpers ============================
__device__ __forceinline__ uint32_t smem_u32(const void* p) {
    uint32_t a;
    asm("{ .reg .u64 t; cvta.to.shared.u64 t, %1; cvt.u32.u64 %0, t; }" : "=r"(a) : "l"(p));
    return a;
}
__device__ __forceinline__ void cp16(uint32_t dst, const void* src) {
    asm volatile("cp.async.cg.shared.global [%0], [%1], 16;" :: "r"(dst), "l"(src));
}
#define CP_COMMIT() asm volatile("cp.async.commit_group;" ::: "memory")
#define CP_WAIT2()  asm volatile("cp.async.wait_group 2;" ::: "memory")

__device__ __forceinline__ void mma_f16(float* d, const uint32_t* a, uint32_t b0, uint32_t b1) {
    asm volatile(
        "mma.sync.aligned.m16n8k16.row.col.f32.f16.f16.f32 "
        "{%0,%1,%2,%3}, {%4,%5,%6,%7}, {%8,%9}, {%0,%1,%2,%3};"
        : "+f"(d[0]), "+f"(d[1]), "+f"(d[2]), "+f"(d[3])
        : "r"(a[0]), "r"(a[1]), "r"(a[2]), "r"(a[3]), "r"(b0), "r"(b1));
}

__device__ __forceinline__ uint32_t packh2(float lo, float hi) {
    __half2 h = __floats2half2_rn(lo, hi);
    return *reinterpret_cast<uint32_t*>(&h);
}

// ============================ prolog kernels ============================
// Permute + fp16-round lm_head_weight [VV, DD] -> g_w pair-packed fragment layout
// (layout/numerics validated in R7/R8).
__global__ void __launch_bounds__(256) wperm_kernel(const float* __restrict__ w,
                                                    uint4* __restrict__ o) {
    int gid = blockIdx.x * 256 + threadIdx.x;      // (VV/8)*128*32 threads
    int lane = gid & 31;
    int ksp  = (gid >> 5) & 127;
    int n8b  = gid >> 12;
    int c = lane & 3;
    int n = n8b * 8 + (lane >> 2);
    const float2* src = reinterpret_cast<const float2*>(w + (size_t)n * DD + ksp * 32 + 2 * c);
    float2 e0 = src[0];    // k = 2c, 2c+1        (even k16, b0)
    float2 e1 = src[4];    // k = 2c+8, 2c+9      (even k16, b1)
    float2 o0 = src[8];    // k = 16+2c, ...      (odd k16, b0)
    float2 o1 = src[12];   // k = 24+2c, ...      (odd k16, b1)
    uint4 v;
    v.x = packh2(e0.x, e0.y);
    v.y = packh2(e1.x, e1.y);
    v.z = packh2(o0.x, o0.y);
    v.w = packh2(o1.x, o1.y);
    o[gid] = v;
}

// RMSNorm one (shifted) row per block, fp16-rounded, A fragment layout.
__global__ void __launch_bounds__(256) rmsperm_kernel(const float* __restrict__ x,
                                                      const float* __restrict__ w,
                                                      uint32_t* __restrict__ o) {
    __shared__ float red[8];
    int r = blockIdx.x, t = threadIdx.x;
    float vals[16];
    if (r < MROWS) {
        int b = r / (SS - 1);
        int s = r - b * (SS - 1);
        const float4* xr = reinterpret_cast<const float4*>(x + ((size_t)b * SS + s) * DD + t * 16);
        const float4* wr = reinterpret_cast<const float4*>(w + t * 16);
        float4 q[4];
        float acc = 0.f;
#pragma unroll
        for (int i = 0; i < 4; ++i) {
            q[i] = xr[i];
            acc += q[i].x * q[i].x + q[i].y * q[i].y + q[i].z * q[i].z + q[i].w * q[i].w;
        }
#pragma unroll
        for (int off = 16; off; off >>= 1) acc += __shfl_xor_sync(0xffffffffu, acc, off);
        if ((t & 31) == 0) red[t >> 5] = acc;
        __syncthreads();
        float tot = red[0] + red[1] + red[2] + red[3] + red[4] + red[5] + red[6] + red[7];
        float rs = rsqrtf(tot * (1.0f / DD) + 1e-6f);
#pragma unroll
        for (int i = 0; i < 4; ++i) {
            float4 wv = wr[i];
            vals[4 * i + 0] = q[i].x * rs * wv.x;
            vals[4 * i + 1] = q[i].y * rs * wv.y;
            vals[4 * i + 2] = q[i].z * rs * wv.z;
            vals[4 * i + 3] = q[i].w * rs * wv.w;
        }
    } else {
#pragma unroll
        for (int i = 0; i < 16; ++i) vals[i] = 0.f;
        __syncthreads();
    }
    int m16 = r >> 4, ri = r & 15;
    int slotb = ri >> 3;
    size_t laneBase = ((size_t)m16 * 256 + t) * 32 + (ri & 7) * 4;
#pragma unroll
    for (int c = 0; c < 4; ++c) {
        size_t li = (laneBase + c) * 4;
        o[li + slotb]     = packh2(vals[2 * c],     vals[2 * c + 1]);
        o[li + slotb + 2] = packh2(vals[2 * c + 8], vals[2 * c + 9]);
    }
}

// Shifted labels -> float32 tail of d_out (layout proven in R3/R4).
__global__ void __launch_bounds__(256) labels_kernel(const int* __restrict__ lab,
                                                     float* __restrict__ out, long long rem) {
    int i = blockIdx.x * blockDim.x + threadIdx.x;
    if (i >= MROWS) return;
    int b = i / (SS - 1);
    int s = i - b * (SS - 1);
    int v = lab[(size_t)b * SS + s + 1];
    size_t base = (size_t)MROWS * VV;
    if (rem >= 2LL * MROWS) {
        reinterpret_cast<long long*>(out + base)[i] = (long long)v;
    } else if (rem >= (long long)MROWS) {
        out[base + i] = (float)v;
    }
}

// ============================ GEMM kernel ============================
// EXACT R6 pipeline structure (proven fastest): grid 8000, wait2 + two syncthreads,
// load-after-compute, static stage counter. Only change vs R6: B pair-packed
// fragments -> 24 LDS per k-block instead of 40.
#define NSTG      3
#define STG_BYTES 32768                 // A 16KB + B 16KB per stage
#define KBLOCKS   (DD / 64)             // 64

__global__ void __launch_bounds__(256, 2) gemm_kernel(const __half* __restrict__ A,
                                                      const __half* __restrict__ B,
                                                      float* __restrict__ out) {
    extern __shared__ char smem[];
    uint32_t sbase = smem_u32(smem);
    int t = threadIdx.x;
    int lane = t & 31, wid = t >> 5;
    int wm = wid & 3, wn = wid >> 2;
    int m_tile = blockIdx.x & 31;       // m fastest: A (32MB fp16) L2-resident
    int n_tile = blockIdx.x >> 5;

    const char* Ab = (const char*)A;
    const char* Bb = (const char*)B;

    // stage fill: pure 16B cp.async copies (gmem fragment layout == smem layout)
    auto load_stage = [&](int st, int kb) {
        uint32_t dstA = sbase + st * STG_BYTES;
        uint32_t dstB = dstA + 16384;
#pragma unroll
        for (int pp = 0; pp < 4; ++pp) {            // A: 1024 x 16B chunks
            int q = pp * 256 + t;                   // q = (m16b*4 + ks)*32 + ln
            int ln = q & 31, ks = (q >> 5) & 3, m16b = q >> 7;
            const char* src = Ab + ((((size_t)(m_tile * 8 + m16b) * 256 + kb * 4 + ks) * 32 + ln) << 4);
            cp16(dstA + (q << 4), src);
        }
#pragma unroll
        for (int pp = 0; pp < 4; ++pp) {            // B: 1024 x 16B chunks
            int q = pp * 256 + t;                   // q = (n8b*2 + kspl)*32 + ln
            int ln = q & 31, kspl = (q >> 5) & 1, n8b = q >> 6;
            const char* src = Bb + ((((size_t)(n_tile * 16 + n8b) * 128 + kb * 2 + kspl) * 32 + ln) << 4);
            cp16(dstB + (q << 4), src);
        }
    };

    float acc[2][8][4];
#pragma unroll
    for (int i = 0; i < 2; ++i)
#pragma unroll
        for (int j = 0; j < 8; ++j)
#pragma unroll
            for (int c = 0; c < 4; ++c) acc[i][j][c] = 0.f;

    // prologue: fill 3 stages
#pragma unroll
    for (int s = 0; s < NSTG; ++s) {
        load_stage(s, s);
        CP_COMMIT();
    }

    int st = 0;
    for (int kb = 0; kb < KBLOCKS; ++kb) {
        CP_WAIT2();
        __syncthreads();
        const uint4* Asp = reinterpret_cast<const uint4*>(smem + st * STG_BYTES);
        const uint4* Bsp = reinterpret_cast<const uint4*>(smem + st * STG_BYTES + 16384);
#pragma unroll
        for (int kspl = 0; kspl < 2; ++kspl) {
            uint4 bf[8];                               // 8 lds.128: B for both ks halves
#pragma unroll
            for (int j = 0; j < 8; ++j)
                bf[j] = Bsp[(((wn * 8 + j) * 2 + kspl) * 32) + lane];
#pragma unroll
            for (int ks2 = 0; ks2 < 2; ++ks2) {
                int ks = kspl * 2 + ks2;
                uint4 a[2];                            // 2 lds.128
#pragma unroll
                for (int i = 0; i < 2; ++i)
                    a[i] = Asp[(((wm * 2 + i) * 4 + ks) * 32) + lane];
#pragma unroll
                for (int i = 0; i < 2; ++i)
#pragma unroll
                    for (int j = 0; j < 8; ++j) {
                        uint32_t b0 = ks2 ? bf[j].z : bf[j].x;   // compile-time select
                        uint32_t b1 = ks2 ? bf[j].w : bf[j].y;
                        mma_f16(acc[i][j], (const uint32_t*)&a[i], b0, b1);
                    }
            }
        }
        __syncthreads();
        if (kb + NSTG < KBLOCKS) load_stage(st, kb + NSTG);
        CP_COMMIT();
        st = (st == NSTG - 1) ? 0 : st + 1;
    }

    // epilogue: fragment layout -> row-major fp32 logits
    int gq = lane >> 2, tq = lane & 3;
#pragma unroll
    for (int i = 0; i < 2; ++i) {
        int r0 = m_tile * 128 + wm * 32 + i * 16 + gq;
#pragma unroll
        for (int j = 0; j < 8; ++j) {
            int col = n_tile * 128 + wn * 64 + j * 8 + tq * 2;
            if (r0 < MROWS)
                *reinterpret_cast<float2*>(out + (size_t)r0 * VV + col) =
                    make_float2(acc[i][j][0], acc[i][j][1]);
            if (r0 + 8 < MROWS)
                *reinterpret_cast<float2*>(out + (size_t)(r0 + 8) * VV + col) =
                    make_float2(acc[i][j][2], acc[i][j][3]);
        }
    }
}

// ============================ host launcher ============================
extern "C" void kernel_launch(void* const* d_in, const int* in_sizes, int n_in,
                              void* d_out, int out_size) {
    const float* hs  = (const float*)d_in[0];
    const float* nw  = (const float*)d_in[1];
    const float* lmw = (const float*)d_in[2];
    const int*   lab = (const int*)d_in[4];
    float* out = (float*)d_out;

    void* act_ptr = nullptr; cudaGetSymbolAddress(&act_ptr, g_act);
    void* w_ptr   = nullptr; cudaGetSymbolAddress(&w_ptr, g_w);

    // prolog: permute/round weights + rmsnorm activations + labels
    wperm_kernel<<<(VV / 8) * 128 * 32 / 256, 256>>>(lmw, (uint4*)w_ptr);
    rmsperm_kernel<<<MPAD, 256>>>(hs, nw, (uint32_t*)act_ptr);
    long long rem = (long long)out_size - (long long)MROWS * VV;
    labels_kernel<<<(MROWS + 255) / 256, 256>>>(lab, out, rem);

    // GEMM: 32 m-tiles x 250 n-tiles (R6 grid)
    cudaFuncSetAttribute(gemm_kernel, cudaFuncAttributeMaxDynamicSharedMemorySize,
                         NSTG * STG_BYTES);
    gemm_kernel<<<32 * 250, 256, NSTG * STG_BYTES>>>((const __half*)act_ptr,
                                                     (const __half*)w_ptr, out);
}

// round 11
// speedup vs baseline: 1.6590x; 1.0188x over previous
#include <cuda_runtime.h>
#include <cuda_fp16.h>
#include <cstdint>

// ============================ problem constants ============================
#define SS 2048
#define DD 4096
#define VV 32000
#define MROWS 4094          // B*(S-1)
#define MPAD  4096          // padded GEMM M

// scratch (device globals — allocation-free rule), fp16 operands
// A fragment layout (mma.m16n8k16 A): [m16_blk(256)][k16(256)][lane(32)][a0..a3] (16B/lane)
__device__ __half g_act[(size_t)MPAD * DD];
// B fragment layout (R6, proven): [n8_blk(4000)][k16(256)][lane(32)][b0,b1] (8B/lane)
__device__ __half g_w[(size_t)VV * DD];

// ============================ helpers ============================
__device__ __forceinline__ uint32_t smem_u32(const void* p) {
    uint32_t a;
    asm("{ .reg .u64 t; cvta.to.shared.u64 t, %1; cvt.u32.u64 %0, t; }" : "=r"(a) : "l"(p));
    return a;
}
__device__ __forceinline__ void cp16(uint32_t dst, const void* src) {
    asm volatile("cp.async.cg.shared.global [%0], [%1], 16;" :: "r"(dst), "l"(src));
}
#define CP_COMMIT() asm volatile("cp.async.commit_group;" ::: "memory")
#define CP_WAIT2()  asm volatile("cp.async.wait_group 2;" ::: "memory")

__device__ __forceinline__ void mma_f16(float* d, const uint32_t* a, const uint32_t* b) {
    asm volatile(
        "mma.sync.aligned.m16n8k16.row.col.f32.f16.f16.f32 "
        "{%0,%1,%2,%3}, {%4,%5,%6,%7}, {%8,%9}, {%0,%1,%2,%3};"
        : "+f"(d[0]), "+f"(d[1]), "+f"(d[2]), "+f"(d[3])
        : "r"(a[0]), "r"(a[1]), "r"(a[2]), "r"(a[3]), "r"(b[0]), "r"(b[1]));
}

__device__ __forceinline__ uint32_t packh2(float lo, float hi) {
    __half2 h = __floats2half2_rn(lo, hi);
    return *reinterpret_cast<uint32_t*>(&h);
}
__device__ __forceinline__ void stcs2(float* p, float x, float y) {
    asm volatile("st.global.cs.v2.f32 [%0], {%1, %2};" :: "l"(p), "f"(x), "f"(y) : "memory");
}

// ============================ prolog kernels ============================
// Permute + fp16-round lm_head_weight [VV, DD] -> g_w fragment layout (R6 layout).
// Each thread handles TWO k16 groups (2x the R6 work) to halve block count.
__global__ void __launch_bounds__(256) wperm_kernel(const float* __restrict__ w,
                                                    uint32_t* __restrict__ o) {
    int gid0 = (blockIdx.x * 256 + threadIdx.x) * 2;   // first of 2 k16-groups
#pragma unroll
    for (int u = 0; u < 2; ++u) {
        int gid = gid0 + u;
        int n  = gid >> 8;
        int kg = gid & 255;                            // k16 step
        const float4* src = reinterpret_cast<const float4*>(w + (size_t)n * DD + kg * 16);
        float4 v0 = src[0], v1 = src[1], v2 = src[2], v3 = src[3];
        float h[16] = { v0.x, v0.y, v0.z, v0.w, v1.x, v1.y, v1.z, v1.w,
                        v2.x, v2.y, v2.z, v2.w, v3.x, v3.y, v3.z, v3.w };
        size_t laneBase = (((size_t)(n >> 3) * 256 + kg) * 32 + (n & 7) * 4);
        uint4* dst = reinterpret_cast<uint4*>(o + laneBase * 2);
        uint4 q0, q1;
        q0.x = packh2(h[0], h[1]);  q0.y = packh2(h[8],  h[9]);    // lane c=0: b0,b1
        q0.z = packh2(h[2], h[3]);  q0.w = packh2(h[10], h[11]);   // lane c=1
        q1.x = packh2(h[4], h[5]);  q1.y = packh2(h[12], h[13]);   // lane c=2
        q1.z = packh2(h[6], h[7]);  q1.w = packh2(h[14], h[15]);   // lane c=3
        dst[0] = q0;
        dst[1] = q1;
    }
}

// RMSNorm one (shifted) row per block, fp16-rounded, A fragment layout (R6, proven).
__global__ void __launch_bounds__(256) rmsperm_kernel(const float* __restrict__ x,
                                                      const float* __restrict__ w,
                                                      uint32_t* __restrict__ o) {
    __shared__ float red[8];
    int r = blockIdx.x, t = threadIdx.x;
    float vals[16];
    if (r < MROWS) {
        int b = r / (SS - 1);
        int s = r - b * (SS - 1);
        const float4* xr = reinterpret_cast<const float4*>(x + ((size_t)b * SS + s) * DD + t * 16);
        const float4* wr = reinterpret_cast<const float4*>(w + t * 16);
        float4 q[4];
        float acc = 0.f;
#pragma unroll
        for (int i = 0; i < 4; ++i) {
            q[i] = xr[i];
            acc += q[i].x * q[i].x + q[i].y * q[i].y + q[i].z * q[i].z + q[i].w * q[i].w;
        }
#pragma unroll
        for (int off = 16; off; off >>= 1) acc += __shfl_xor_sync(0xffffffffu, acc, off);
        if ((t & 31) == 0) red[t >> 5] = acc;
        __syncthreads();
        float tot = red[0] + red[1] + red[2] + red[3] + red[4] + red[5] + red[6] + red[7];
        float rs = rsqrtf(tot * (1.0f / DD) + 1e-6f);
#pragma unroll
        for (int i = 0; i < 4; ++i) {
            float4 wv = wr[i];
            vals[4 * i + 0] = q[i].x * rs * wv.x;
            vals[4 * i + 1] = q[i].y * rs * wv.y;
            vals[4 * i + 2] = q[i].z * rs * wv.z;
            vals[4 * i + 3] = q[i].w * rs * wv.w;
        }
    } else {
#pragma unroll
        for (int i = 0; i < 16; ++i) vals[i] = 0.f;
        __syncthreads();
    }
    int m16 = r >> 4, ri = r & 15;
    int slotb = ri >> 3;
    size_t laneBase = ((size_t)m16 * 256 + t) * 32 + (ri & 7) * 4;
#pragma unroll
    for (int c = 0; c < 4; ++c) {
        size_t li = (laneBase + c) * 4;
        o[li + slotb]     = packh2(vals[2 * c],     vals[2 * c + 1]);
        o[li + slotb + 2] = packh2(vals[2 * c + 8], vals[2 * c + 9]);
    }
}

// Shifted labels -> float32 tail of d_out (layout proven in R3/R4).
__global__ void __launch_bounds__(256) labels_kernel(const int* __restrict__ lab,
                                                     float* __restrict__ out, long long rem) {
    int i = blockIdx.x * blockDim.x + threadIdx.x;
    if (i >= MROWS) return;
    int b = i / (SS - 1);
    int s = i - b * (SS - 1);
    int v = lab[(size_t)b * SS + s + 1];
    size_t base = (size_t)MROWS * VV;
    if (rem >= 2LL * MROWS) {
        reinterpret_cast<long long*>(out + base)[i] = (long long)v;
    } else if (rem >= (long long)MROWS) {
        out[base + i] = (float)v;
    }
}

// ============================ GEMM kernel ============================
// EXACT R6 hot loop (proven fastest: 2533us total). Epilogue-only changes:
// branchless fast path for m_tile != 31 and .cs streaming stores.
#define NSTG      3
#define STG_BYTES 32768                 // A 16KB + B 16KB per stage
#define KBLOCKS   (DD / 64)             // 64

__global__ void __launch_bounds__(256, 2) gemm_kernel(const __half* __restrict__ A,
                                                      const __half* __restrict__ B,
                                                      float* __restrict__ out) {
    extern __shared__ char smem[];
    uint32_t sbase = smem_u32(smem);
    int t = threadIdx.x;
    int lane = t & 31, wid = t >> 5;
    int wm = wid & 3, wn = wid >> 2;
    int m_tile = blockIdx.x & 31;       // m fastest: A (32MB fp16) L2-resident
    int n_tile = blockIdx.x >> 5;

    const char* Ab = (const char*)A;
    const char* Bb = (const char*)B;

    // stage fill: pure 16B cp.async copies (gmem fragment layout == smem layout)
    auto load_stage = [&](int st, int kb) {
        uint32_t dstA = sbase + st * STG_BYTES;
        uint32_t dstB = dstA + 16384;
#pragma unroll
        for (int pp = 0; pp < 4; ++pp) {            // A: 1024 x 16B chunks
            int q = pp * 256 + t;
            int ln = q & 31, ks = (q >> 5) & 3, m16b = q >> 7;
            const char* src = Ab + ((((size_t)(m_tile * 8 + m16b) * 256 + kb * 4 + ks) * 32 + ln) << 4);
            cp16(dstA + (q << 4), src);
        }
#pragma unroll
        for (int pp = 0; pp < 4; ++pp) {            // B: 1024 x 16B chunks (2 lanes each)
            int q = pp * 256 + t;
            int ln2 = q & 15, ks = (q >> 4) & 3, n8b = q >> 6;
            const char* src = Bb + ((((size_t)(n_tile * 16 + n8b) * 256 + kb * 4 + ks) * 32 + ln2 * 2) << 3);
            cp16(dstB + (q << 4), src);
        }
    };

    float acc[2][8][4];
#pragma unroll
    for (int i = 0; i < 2; ++i)
#pragma unroll
        for (int j = 0; j < 8; ++j)
#pragma unroll
            for (int c = 0; c < 4; ++c) acc[i][j][c] = 0.f;

#pragma unroll
    for (int s = 0; s < NSTG; ++s) {
        load_stage(s, s);
        CP_COMMIT();
    }

    int st = 0;
    for (int kb = 0; kb < KBLOCKS; ++kb) {
        CP_WAIT2();
        __syncthreads();
        const uint4* Asp = reinterpret_cast<const uint4*>(smem + st * STG_BYTES);
        const uint2* Bsp = reinterpret_cast<const uint2*>(smem + st * STG_BYTES + 16384);
#pragma unroll
        for (int ks = 0; ks < 4; ++ks) {
            uint4 a[2];
            uint2 b[8];
#pragma unroll
            for (int i = 0; i < 2; ++i)
                a[i] = Asp[(((wm * 2 + i) * 4 + ks) * 32) + lane];
#pragma unroll
            for (int j = 0; j < 8; ++j)
                b[j] = Bsp[(((wn * 8 + j) * 4 + ks) * 32) + lane];
#pragma unroll
            for (int i = 0; i < 2; ++i)
#pragma unroll
                for (int j = 0; j < 8; ++j)
                    mma_f16(acc[i][j], (const uint32_t*)&a[i], (const uint32_t*)&b[j]);
        }
        __syncthreads();
        if (kb + NSTG < KBLOCKS) load_stage(st, kb + NSTG);
        CP_COMMIT();
        st = (st == NSTG - 1) ? 0 : st + 1;
    }

    // epilogue: fragment layout -> row-major fp32 logits (.cs: write-once stream)
    int gq = lane >> 2, tq = lane & 3;
    if (m_tile != 31) {                 // all rows valid: branchless stores
#pragma unroll
        for (int i = 0; i < 2; ++i) {
            int r0 = m_tile * 128 + wm * 32 + i * 16 + gq;
#pragma unroll
            for (int j = 0; j < 8; ++j) {
                int col = n_tile * 128 + wn * 64 + j * 8 + tq * 2;
                stcs2(out + (size_t)r0 * VV + col,       acc[i][j][0], acc[i][j][1]);
                stcs2(out + (size_t)(r0 + 8) * VV + col, acc[i][j][2], acc[i][j][3]);
            }
        }
    } else {
#pragma unroll
        for (int i = 0; i < 2; ++i) {
            int r0 = m_tile * 128 + wm * 32 + i * 16 + gq;
#pragma unroll
            for (int j = 0; j < 8; ++j) {
                int col = n_tile * 128 + wn * 64 + j * 8 + tq * 2;
                if (r0 < MROWS)
                    stcs2(out + (size_t)r0 * VV + col, acc[i][j][0], acc[i][j][1]);
                if (r0 + 8 < MROWS)
                    stcs2(out + (size_t)(r0 + 8) * VV + col, acc[i][j][2], acc[i][j][3]);
            }
        }
    }
}

// ============================ host launcher ============================
extern "C" void kernel_launch(void* const* d_in, const int* in_sizes, int n_in,
                              void* d_out, int out_size) {
    const float* hs  = (const float*)d_in[0];
    const float* nw  = (const float*)d_in[1];
    const float* lmw = (const float*)d_in[2];
    const int*   lab = (const int*)d_in[4];
    float* out = (float*)d_out;

    void* act_ptr = nullptr; cudaGetSymbolAddress(&act_ptr, g_act);
    void* w_ptr   = nullptr; cudaGetSymbolAddress(&w_ptr, g_w);

    // prolog: permute/round weights + rmsnorm activations + labels
    wperm_kernel<<<VV / 2, 256>>>(lmw, (uint32_t*)w_ptr);       // 2 k16-groups/thread
    rmsperm_kernel<<<MPAD, 256>>>(hs, nw, (uint32_t*)act_ptr);
    long long rem = (long long)out_size - (long long)MROWS * VV;
    labels_kernel<<<(MROWS + 255) / 256, 256>>>(lab, out, rem);

    // GEMM: 32 m-tiles x 250 n-tiles (R6 grid)
    cudaFuncSetAttribute(gemm_kernel, cudaFuncAttributeMaxDynamicSharedMemorySize,
                         NSTG * STG_BYTES);
    gemm_kernel<<<32 * 250, 256, NSTG * STG_BYTES>>>((const __half*)act_ptr,
                                                     (const __half*)w_ptr, out);
}

// round 12
// speedup vs baseline: 1.6959x; 1.0222x over previous
#include <cuda_runtime.h>
#include <cuda_fp16.h>
#include <cstdint>

// ============================ problem constants ============================
#define SS 2048
#define DD 4096
#define VV 32000
#define MROWS 4094          // B*(S-1)
#define MPAD  4096          // padded GEMM M

// scratch (device globals — allocation-free rule), fp16 operands
// A fragment layout (mma.m16n8k16 A): [m16_blk(256)][k16(256)][lane(32)][a0..a3] (16B/lane)
__device__ __half g_act[(size_t)MPAD * DD];
// B fragment layout (R6, proven): [n8_blk(4000)][k16(256)][lane(32)][b0,b1] (8B/lane)
__device__ __half g_w[(size_t)VV * DD];

// ============================ helpers ============================
__device__ __forceinline__ uint32_t smem_u32(const void* p) {
    uint32_t a;
    asm("{ .reg .u64 t; cvta.to.shared.u64 t, %1; cvt.u32.u64 %0, t; }" : "=r"(a) : "l"(p));
    return a;
}
__device__ __forceinline__ void cp16(uint32_t dst, const void* src) {
    asm volatile("cp.async.cg.shared.global [%0], [%1], 16;" :: "r"(dst), "l"(src));
}
#define CP_COMMIT() asm volatile("cp.async.commit_group;" ::: "memory")
#define CP_WAIT2()  asm volatile("cp.async.wait_group 2;" ::: "memory")

__device__ __forceinline__ void mma_f16(float* d, const uint32_t* a, const uint32_t* b) {
    asm volatile(
        "mma.sync.aligned.m16n8k16.row.col.f32.f16.f16.f32 "
        "{%0,%1,%2,%3}, {%4,%5,%6,%7}, {%8,%9}, {%0,%1,%2,%3};"
        : "+f"(d[0]), "+f"(d[1]), "+f"(d[2]), "+f"(d[3])
        : "r"(a[0]), "r"(a[1]), "r"(a[2]), "r"(a[3]), "r"(b[0]), "r"(b[1]));
}

__device__ __forceinline__ uint32_t packh2(float lo, float hi) {
    __half2 h = __floats2half2_rn(lo, hi);
    return *reinterpret_cast<uint32_t*>(&h);
}
__device__ __forceinline__ void stcs4(uint4* p, uint4 v) {
    asm volatile("st.global.cs.v4.b32 [%0], {%1, %2, %3, %4};"
                 :: "l"(p), "r"(v.x), "r"(v.y), "r"(v.z), "r"(v.w) : "memory");
}

// ============================ prolog kernels ============================
// Permute + fp16-round lm_head_weight [VV, DD] -> g_w fragment layout.
// EXACT R6 structure (one thread per (n, k16-group)); only delta: streaming
// load/store hints (.cs) — weights read once, g_w >> L2.
__global__ void __launch_bounds__(256) wperm_kernel(const float* __restrict__ w,
                                                    uint32_t* __restrict__ o) {
    int gid = blockIdx.x * 256 + threadIdx.x;      // VV * 256 threads
    int n  = gid >> 8;
    int kg = gid & 255;                            // k16 step
    const float4* src = reinterpret_cast<const float4*>(w + (size_t)n * DD + kg * 16);
    float4 v0 = __ldcs(src + 0), v1 = __ldcs(src + 1);
    float4 v2 = __ldcs(src + 2), v3 = __ldcs(src + 3);
    float h[16] = { v0.x, v0.y, v0.z, v0.w, v1.x, v1.y, v1.z, v1.w,
                    v2.x, v2.y, v2.z, v2.w, v3.x, v3.y, v3.z, v3.w };
    size_t laneBase = (((size_t)(n >> 3) * 256 + kg) * 32 + (n & 7) * 4);
    uint4* dst = reinterpret_cast<uint4*>(o + laneBase * 2);
    uint4 q0, q1;
    q0.x = packh2(h[0], h[1]);  q0.y = packh2(h[8],  h[9]);    // lane c=0: b0,b1
    q0.z = packh2(h[2], h[3]);  q0.w = packh2(h[10], h[11]);   // lane c=1
    q1.x = packh2(h[4], h[5]);  q1.y = packh2(h[12], h[13]);   // lane c=2
    q1.z = packh2(h[6], h[7]);  q1.w = packh2(h[14], h[15]);   // lane c=3
    stcs4(dst + 0, q0);
    stcs4(dst + 1, q1);
}

// RMSNorm one (shifted) row per block, fp16-rounded, A fragment layout (R6, proven).
// Labels folded in: block r also writes shift_labels[r] (saves a kernel launch).
__global__ void __launch_bounds__(256) rmsperm_kernel(const float* __restrict__ x,
                                                      const float* __restrict__ w,
                                                      uint32_t* __restrict__ o,
                                                      const int* __restrict__ lab,
                                                      float* __restrict__ out,
                                                      long long rem) {
    __shared__ float red[8];
    int r = blockIdx.x, t = threadIdx.x;
    float vals[16];
    if (r < MROWS) {
        int b = r / (SS - 1);
        int s = r - b * (SS - 1);
        if (t == 224) {   // labels: one thread per block, independent of the rest
            int v = lab[(size_t)b * SS + s + 1];
            size_t base = (size_t)MROWS * VV;
            if (rem >= 2LL * MROWS) {
                reinterpret_cast<long long*>(out + base)[r] = (long long)v;
            } else if (rem >= (long long)MROWS) {
                out[base + r] = (float)v;   // float32 tail (actual layout, R4-proven)
            }
        }
        const float4* xr = reinterpret_cast<const float4*>(x + ((size_t)b * SS + s) * DD + t * 16);
        const float4* wr = reinterpret_cast<const float4*>(w + t * 16);
        float4 q[4];
        float acc = 0.f;
#pragma unroll
        for (int i = 0; i < 4; ++i) {
            q[i] = xr[i];
            acc += q[i].x * q[i].x + q[i].y * q[i].y + q[i].z * q[i].z + q[i].w * q[i].w;
        }
#pragma unroll
        for (int off = 16; off; off >>= 1) acc += __shfl_xor_sync(0xffffffffu, acc, off);
        if ((t & 31) == 0) red[t >> 5] = acc;
        __syncthreads();
        float tot = red[0] + red[1] + red[2] + red[3] + red[4] + red[5] + red[6] + red[7];
        float rs = rsqrtf(tot * (1.0f / DD) + 1e-6f);
#pragma unroll
        for (int i = 0; i < 4; ++i) {
            float4 wv = wr[i];
            vals[4 * i + 0] = q[i].x * rs * wv.x;
            vals[4 * i + 1] = q[i].y * rs * wv.y;
            vals[4 * i + 2] = q[i].z * rs * wv.z;
            vals[4 * i + 3] = q[i].w * rs * wv.w;
        }
    } else {
#pragma unroll
        for (int i = 0; i < 16; ++i) vals[i] = 0.f;
        __syncthreads();   // keep barrier count uniform
    }
    int m16 = r >> 4, ri = r & 15;
    int slotb = ri >> 3;
    size_t laneBase = ((size_t)m16 * 256 + t) * 32 + (ri & 7) * 4;
#pragma unroll
    for (int c = 0; c < 4; ++c) {
        size_t li = (laneBase + c) * 4;
        o[li + slotb]     = packh2(vals[2 * c],     vals[2 * c + 1]);
        o[li + slotb + 2] = packh2(vals[2 * c + 8], vals[2 * c + 9]);
    }
}

// ============================ GEMM kernel ============================
// EXACT R6 (proven fastest: gemm 2348us): grid 8000, kBlock 64, NSTG 3,
// wait2 + two syncthreads, load-after-compute, R6 epilogue.
#define NSTG      3
#define STG_BYTES 32768                 // A 16KB + B 16KB per stage
#define KBLOCKS   (DD / 64)             // 64

__global__ void __launch_bounds__(256, 2) gemm_kernel(const __half* __restrict__ A,
                                                      const __half* __restrict__ B,
                                                      float* __restrict__ out) {
    extern __shared__ char smem[];
    uint32_t sbase = smem_u32(smem);
    int t = threadIdx.x;
    int lane = t & 31, wid = t >> 5;
    int wm = wid & 3, wn = wid >> 2;
    int m_tile = blockIdx.x & 31;       // m fastest: A (32MB fp16) L2-resident
    int n_tile = blockIdx.x >> 5;

    const char* Ab = (const char*)A;
    const char* Bb = (const char*)B;

    auto load_stage = [&](int st, int kb) {
        uint32_t dstA = sbase + st * STG_BYTES;
        uint32_t dstB = dstA + 16384;
#pragma unroll
        for (int pp = 0; pp < 4; ++pp) {            // A: 1024 x 16B chunks
            int q = pp * 256 + t;
            int ln = q & 31, ks = (q >> 5) & 3, m16b = q >> 7;
            const char* src = Ab + ((((size_t)(m_tile * 8 + m16b) * 256 + kb * 4 + ks) * 32 + ln) << 4);
            cp16(dstA + (q << 4), src);
        }
#pragma unroll
        for (int pp = 0; pp < 4; ++pp) {            // B: 1024 x 16B chunks (2 lanes each)
            int q = pp * 256 + t;
            int ln2 = q & 15, ks = (q >> 4) & 3, n8b = q >> 6;
            const char* src = Bb + ((((size_t)(n_tile * 16 + n8b) * 256 + kb * 4 + ks) * 32 + ln2 * 2) << 3);
            cp16(dstB + (q << 4), src);
        }
    };

    float acc[2][8][4];
#pragma unroll
    for (int i = 0; i < 2; ++i)
#pragma unroll
        for (int j = 0; j < 8; ++j)
#pragma unroll
            for (int c = 0; c < 4; ++c) acc[i][j][c] = 0.f;

#pragma unroll
    for (int s = 0; s < NSTG; ++s) {
        load_stage(s, s);
        CP_COMMIT();
    }

    int st = 0;
    for (int kb = 0; kb < KBLOCKS; ++kb) {
        CP_WAIT2();
        __syncthreads();
        const uint4* Asp = reinterpret_cast<const uint4*>(smem + st * STG_BYTES);
        const uint2* Bsp = reinterpret_cast<const uint2*>(smem + st * STG_BYTES + 16384);
#pragma unroll
        for (int ks = 0; ks < 4; ++ks) {
            uint4 a[2];
            uint2 b[8];
#pragma unroll
            for (int i = 0; i < 2; ++i)
                a[i] = Asp[(((wm * 2 + i) * 4 + ks) * 32) + lane];
#pragma unroll
            for (int j = 0; j < 8; ++j)
                b[j] = Bsp[(((wn * 8 + j) * 4 + ks) * 32) + lane];
#pragma unroll
            for (int i = 0; i < 2; ++i)
#pragma unroll
                for (int j = 0; j < 8; ++j)
                    mma_f16(acc[i][j], (const uint32_t*)&a[i], (const uint32_t*)&b[j]);
        }
        __syncthreads();
        if (kb + NSTG < KBLOCKS) load_stage(st, kb + NSTG);
        CP_COMMIT();
        st = (st == NSTG - 1) ? 0 : st + 1;
    }

    // epilogue: fragment layout -> row-major fp32 logits (exact R6)
    int gq = lane >> 2, tq = lane & 3;
#pragma unroll
    for (int i = 0; i < 2; ++i) {
        int r0 = m_tile * 128 + wm * 32 + i * 16 + gq;
#pragma unroll
        for (int j = 0; j < 8; ++j) {
            int col = n_tile * 128 + wn * 64 + j * 8 + tq * 2;
            if (r0 < MROWS)
                *reinterpret_cast<float2*>(out + (size_t)r0 * VV + col) =
                    make_float2(acc[i][j][0], acc[i][j][1]);
            if (r0 + 8 < MROWS)
                *reinterpret_cast<float2*>(out + (size_t)(r0 + 8) * VV + col) =
                    make_float2(acc[i][j][2], acc[i][j][3]);
        }
    }
}

// ============================ host launcher ============================
extern "C" void kernel_launch(void* const* d_in, const int* in_sizes, int n_in,
                              void* d_out, int out_size) {
    const float* hs  = (const float*)d_in[0];
    const float* nw  = (const float*)d_in[1];
    const float* lmw = (const float*)d_in[2];
    const int*   lab = (const int*)d_in[4];
    float* out = (float*)d_out;

    void* act_ptr = nullptr; cudaGetSymbolAddress(&act_ptr, g_act);
    void* w_ptr   = nullptr; cudaGetSymbolAddress(&w_ptr, g_w);

    // prolog: permute/round weights + rmsnorm (labels folded in)
    long long rem = (long long)out_size - (long long)MROWS * VV;
    wperm_kernel<<<VV, 256>>>(lmw, (uint32_t*)w_ptr);
    rmsperm_kernel<<<MPAD, 256>>>(hs, nw, (uint32_t*)act_ptr, lab, out, rem);

    // GEMM: 32 m-tiles x 250 n-tiles (R6 grid)
    cudaFuncSetAttribute(gemm_kernel, cudaFuncAttributeMaxDynamicSharedMemorySize,
                         NSTG * STG_BYTES);
    gemm_kernel<<<32 * 250, 256, NSTG * STG_BYTES>>>((const __half*)act_ptr,
                                                     (const __half*)w_ptr, out);
}

// round 13
// speedup vs baseline: 1.7162x; 1.0120x over previous
#include <cuda_runtime.h>
#include <cuda_fp16.h>
#include <cstdint>

// ============================ problem constants ============================
#define SS 2048
#define DD 4096
#define VV 32000
#define MROWS 4094          // B*(S-1)
#define MPAD  4096          // padded GEMM M

// scratch (device globals — allocation-free rule), fp16 operands
// A fragment layout (mma.m16n8k16 A): [m16_blk(256)][k16(256)][lane(32)][a0..a3] (16B/lane)
__device__ __half g_act[(size_t)MPAD * DD];
// B fragment layout (R6, proven): [n8_blk(4000)][k16(256)][lane(32)][b0,b1] (8B/lane)
__device__ __half g_w[(size_t)VV * DD];

// ============================ helpers ============================
__device__ __forceinline__ uint32_t smem_u32(const void* p) {
    uint32_t a;
    asm("{ .reg .u64 t; cvta.to.shared.u64 t, %1; cvt.u32.u64 %0, t; }" : "=r"(a) : "l"(p));
    return a;
}
__device__ __forceinline__ void cp16(uint32_t dst, const void* src) {
    asm volatile("cp.async.cg.shared.global [%0], [%1], 16;" :: "r"(dst), "l"(src));
}
#define CP_COMMIT() asm volatile("cp.async.commit_group;" ::: "memory")
#define CP_WAIT2()  asm volatile("cp.async.wait_group 2;" ::: "memory")

__device__ __forceinline__ void mma_f16(float* d, const uint32_t* a, const uint32_t* b) {
    asm volatile(
        "mma.sync.aligned.m16n8k16.row.col.f32.f16.f16.f32 "
        "{%0,%1,%2,%3}, {%4,%5,%6,%7}, {%8,%9}, {%0,%1,%2,%3};"
        : "+f"(d[0]), "+f"(d[1]), "+f"(d[2]), "+f"(d[3])
        : "r"(a[0]), "r"(a[1]), "r"(a[2]), "r"(a[3]), "r"(b[0]), "r"(b[1]));
}

__device__ __forceinline__ uint32_t packh2(float lo, float hi) {
    __half2 h = __floats2half2_rn(lo, hi);
    return *reinterpret_cast<uint32_t*>(&h);
}
__device__ __forceinline__ void stcs2(uint32_t* p, uint32_t x, uint32_t y) {
    asm volatile("st.global.cs.v2.b32 [%0], {%1, %2};" :: "l"(p), "r"(x), "r"(y) : "memory");
}

// ============================ prolog kernels ============================
// Permute + fp16-round lm_head_weight [VV, DD] -> g_w fragment layout.
// v3: smem transpose so BOTH gmem directions are fully coalesced.
// Block = one n8-row-group x 32 k16-groups (8 rows x 512 cols fp32 = 16KB in,
// 1024 fragment entries x 8B = 8KB out, 256B-contiguous per warp-store).
#define WP_STRIDE 520      // 512 + 8 pad: smem bank spread (2-way max on reads)
__global__ void __launch_bounds__(256) wperm_kernel(const float* __restrict__ w,
                                                    uint32_t* __restrict__ o) {
    __shared__ float s[8 * WP_STRIDE];
    int blk = blockIdx.x;
    int n8b = blk >> 3;
    int kgbase = (blk & 7) * 32;           // first of this block's 32 k16-groups
    int t = threadIdx.x;

    // phase 1: coalesced row reads -> smem
    {
        int r8 = t >> 5, f4 = t & 31;      // row 0-7, float4 column slot
        const float4* src = reinterpret_cast<const float4*>(
            w + ((size_t)(n8b * 8 + r8)) * DD + kgbase * 16);
        float* srow = s + r8 * WP_STRIDE;
#pragma unroll
        for (int it = 0; it < 4; ++it) {
            float4 v = __ldcs(src + it * 32 + f4);
            int ci = (it * 32 + f4) * 4;
            *reinterpret_cast<float4*>(srow + ci) = v;   // 16B-aligned (2080B row)
        }
    }
    __syncthreads();

    // phase 2: gather fragments from smem, 256B-contiguous warp stores
    {
        int ln = t & 31, w8 = t >> 5;
        int nl = ln >> 2, c = ln & 3;      // fragment source: row nl, column group c
        const float* srow = s + nl * WP_STRIDE;
#pragma unroll
        for (int j = 0; j < 4; ++j) {
            int kgl = w8 * 4 + j;          // warp w8 handles k16-groups 4*w8..4*w8+3
            float2 lo = *reinterpret_cast<const float2*>(srow + kgl * 16 + 2 * c);
            float2 hi = *reinterpret_cast<const float2*>(srow + kgl * 16 + 2 * c + 8);
            uint32_t b0 = packh2(lo.x, lo.y);
            uint32_t b1 = packh2(hi.x, hi.y);
            size_t ent = ((size_t)n8b * 256 + kgbase + kgl) * 32 + ln;
            stcs2(o + ent * 2, b0, b1);
        }
    }
}

// RMSNorm one (shifted) row per block, fp16-rounded, A fragment layout (R6, proven).
// Labels folded in (R12, proven): block r also writes shift_labels[r].
__global__ void __launch_bounds__(256) rmsperm_kernel(const float* __restrict__ x,
                                                      const float* __restrict__ w,
                                                      uint32_t* __restrict__ o,
                                                      const int* __restrict__ lab,
                                                      float* __restrict__ out,
                                                      long long rem) {
    __shared__ float red[8];
    int r = blockIdx.x, t = threadIdx.x;
    float vals[16];
    if (r < MROWS) {
        int b = r / (SS - 1);
        int s = r - b * (SS - 1);
        if (t == 224) {   // labels: one thread per block, independent of the rest
            int v = lab[(size_t)b * SS + s + 1];
            size_t base = (size_t)MROWS * VV;
            if (rem >= 2LL * MROWS) {
                reinterpret_cast<long long*>(out + base)[r] = (long long)v;
            } else if (rem >= (long long)MROWS) {
                out[base + r] = (float)v;   // float32 tail (actual layout, R4-proven)
            }
        }
        const float4* xr = reinterpret_cast<const float4*>(x + ((size_t)b * SS + s) * DD + t * 16);
        const float4* wr = reinterpret_cast<const float4*>(w + t * 16);
        float4 q[4];
        float acc = 0.f;
#pragma unroll
        for (int i = 0; i < 4; ++i) {
            q[i] = xr[i];
            acc += q[i].x * q[i].x + q[i].y * q[i].y + q[i].z * q[i].z + q[i].w * q[i].w;
        }
#pragma unroll
        for (int off = 16; off; off >>= 1) acc += __shfl_xor_sync(0xffffffffu, acc, off);
        if ((t & 31) == 0) red[t >> 5] = acc;
        __syncthreads();
        float tot = red[0] + red[1] + red[2] + red[3] + red[4] + red[5] + red[6] + red[7];
        float rs = rsqrtf(tot * (1.0f / DD) + 1e-6f);
#pragma unroll
        for (int i = 0; i < 4; ++i) {
            float4 wv = wr[i];
            vals[4 * i + 0] = q[i].x * rs * wv.x;
            vals[4 * i + 1] = q[i].y * rs * wv.y;
            vals[4 * i + 2] = q[i].z * rs * wv.z;
            vals[4 * i + 3] = q[i].w * rs * wv.w;
        }
    } else {
#pragma unroll
        for (int i = 0; i < 16; ++i) vals[i] = 0.f;
        __syncthreads();   // keep barrier count uniform
    }
    int m16 = r >> 4, ri = r & 15;
    int slotb = ri >> 3;
    size_t laneBase = ((size_t)m16 * 256 + t) * 32 + (ri & 7) * 4;
#pragma unroll
    for (int c = 0; c < 4; ++c) {
        size_t li = (laneBase + c) * 4;
        o[li + slotb]     = packh2(vals[2 * c],     vals[2 * c + 1]);
        o[li + slotb + 2] = packh2(vals[2 * c + 8], vals[2 * c + 9]);
    }
}

// ============================ GEMM kernel ============================
// EXACT R6 (proven fastest: gemm ~2350us): grid 8000, kBlock 64, NSTG 3,
// wait2 + two syncthreads, load-after-compute, R6 epilogue. DO NOT TOUCH.
#define NSTG      3
#define STG_BYTES 32768                 // A 16KB + B 16KB per stage
#define KBLOCKS   (DD / 64)             // 64

__global__ void __launch_bounds__(256, 2) gemm_kernel(const __half* __restrict__ A,
                                                      const __half* __restrict__ B,
                                                      float* __restrict__ out) {
    extern __shared__ char smem[];
    uint32_t sbase = smem_u32(smem);
    int t = threadIdx.x;
    int lane = t & 31, wid = t >> 5;
    int wm = wid & 3, wn = wid >> 2;
    int m_tile = blockIdx.x & 31;       // m fastest: A (32MB fp16) L2-resident
    int n_tile = blockIdx.x >> 5;

    const char* Ab = (const char*)A;
    const char* Bb = (const char*)B;

    auto load_stage = [&](int st, int kb) {
        uint32_t dstA = sbase + st * STG_BYTES;
        uint32_t dstB = dstA + 16384;
#pragma unroll
        for (int pp = 0; pp < 4; ++pp) {            // A: 1024 x 16B chunks
            int q = pp * 256 + t;
            int ln = q & 31, ks = (q >> 5) & 3, m16b = q >> 7;
            const char* src = Ab + ((((size_t)(m_tile * 8 + m16b) * 256 + kb * 4 + ks) * 32 + ln) << 4);
            cp16(dstA + (q << 4), src);
        }
#pragma unroll
        for (int pp = 0; pp < 4; ++pp) {            // B: 1024 x 16B chunks (2 lanes each)
            int q = pp * 256 + t;
            int ln2 = q & 15, ks = (q >> 4) & 3, n8b = q >> 6;
            const char* src = Bb + ((((size_t)(n_tile * 16 + n8b) * 256 + kb * 4 + ks) * 32 + ln2 * 2) << 3);
            cp16(dstB + (q << 4), src);
        }
    };

    float acc[2][8][4];
#pragma unroll
    for (int i = 0; i < 2; ++i)
#pragma unroll
        for (int j = 0; j < 8; ++j)
#pragma unroll
            for (int c = 0; c < 4; ++c) acc[i][j][c] = 0.f;

#pragma unroll
    for (int s = 0; s < NSTG; ++s) {
        load_stage(s, s);
        CP_COMMIT();
    }

    int st = 0;
    for (int kb = 0; kb < KBLOCKS; ++kb) {
        CP_WAIT2();
        __syncthreads();
        const uint4* Asp = reinterpret_cast<const uint4*>(smem + st * STG_BYTES);
        const uint2* Bsp = reinterpret_cast<const uint2*>(smem + st * STG_BYTES + 16384);
#pragma unroll
        for (int ks = 0; ks < 4; ++ks) {
            uint4 a[2];
            uint2 b[8];
#pragma unroll
            for (int i = 0; i < 2; ++i)
                a[i] = Asp[(((wm * 2 + i) * 4 + ks) * 32) + lane];
#pragma unroll
            for (int j = 0; j < 8; ++j)
                b[j] = Bsp[(((wn * 8 + j) * 4 + ks) * 32) + lane];
#pragma unroll
            for (int i = 0; i < 2; ++i)
#pragma unroll
                for (int j = 0; j < 8; ++j)
                    mma_f16(acc[i][j], (const uint32_t*)&a[i], (const uint32_t*)&b[j]);
        }
        __syncthreads();
        if (kb + NSTG < KBLOCKS) load_stage(st, kb + NSTG);
        CP_COMMIT();
        st = (st == NSTG - 1) ? 0 : st + 1;
    }

    // epilogue: fragment layout -> row-major fp32 logits (exact R6)
    int gq = lane >> 2, tq = lane & 3;
#pragma unroll
    for (int i = 0; i < 2; ++i) {
        int r0 = m_tile * 128 + wm * 32 + i * 16 + gq;
#pragma unroll
        for (int j = 0; j < 8; ++j) {
            int col = n_tile * 128 + wn * 64 + j * 8 + tq * 2;
            if (r0 < MROWS)
                *reinterpret_cast<float2*>(out + (size_t)r0 * VV + col) =
                    make_float2(acc[i][j][0], acc[i][j][1]);
            if (r0 + 8 < MROWS)
                *reinterpret_cast<float2*>(out + (size_t)(r0 + 8) * VV + col) =
                    make_float2(acc[i][j][2], acc[i][j][3]);
        }
    }
}

// ============================ host launcher ============================
extern "C" void kernel_launch(void* const* d_in, const int* in_sizes, int n_in,
                              void* d_out, int out_size) {
    const float* hs  = (const float*)d_in[0];
    const float* nw  = (const float*)d_in[1];
    const float* lmw = (const float*)d_in[2];
    const int*   lab = (const int*)d_in[4];
    float* out = (float*)d_out;

    void* act_ptr = nullptr; cudaGetSymbolAddress(&act_ptr, g_act);
    void* w_ptr   = nullptr; cudaGetSymbolAddress(&w_ptr, g_w);

    // prolog: permute/round weights + rmsnorm (labels folded in)
    long long rem = (long long)out_size - (long long)MROWS * VV;
    wperm_kernel<<<(VV / 8) * 8, 256>>>(lmw, (uint32_t*)w_ptr);   // 32000 blocks
    rmsperm_kernel<<<MPAD, 256>>>(hs, nw, (uint32_t*)act_ptr, lab, out, rem);

    // GEMM: 32 m-tiles x 250 n-tiles (R6 grid)
    cudaFuncSetAttribute(gemm_kernel, cudaFuncAttributeMaxDynamicSharedMemorySize,
                         NSTG * STG_BYTES);
    gemm_kernel<<<32 * 250, 256, NSTG * STG_BYTES>>>((const __half*)act_ptr,
                                                     (const __half*)w_ptr, out);
}